// round 2
// baseline (speedup 1.0000x reference)
#include <cuda_runtime.h>
#include <cstdint>
#include <cstddef>

// Problem constants
#define Bb 4
#define Hh 16
#define Ss 2048
#define Dd 64

#define QT 16      // queries per CTA
#define KT 128     // keys per k-tile
#define KPAD 68    // K/Q smem row stride in floats (17 x 16B superbanks -> conflict-free)
#define VPAD 132   // V^T smem row stride in floats (33 x 16B superbanks)
#define NTHREADS 256

// smem layout (floats):
//  Qs  [QT][KPAD]          = 1088
//  Ks  [KT][KPAD]          = 8704
//  VT  [Dd][VPAD]          = 8448
//  P   [QT][Ss]            = 32768
//  rs  [QT]                = 16
#define OFF_QS 0
#define OFF_KS (OFF_QS + QT*KPAD)
#define OFF_VT (OFF_KS + KT*KPAD)
#define OFF_P  (OFF_VT + Dd*VPAD)
#define OFF_RS (OFF_P  + QT*Ss)
#define SMEM_FLOATS (OFF_RS + QT)
#define SMEM_BYTES (SMEM_FLOATS * 4)

// Mask dtype detection results (written by detector kernel, read by main kernel).
// Flag byte for mask element idx lives at byte index (idx << g_mask_shift) + g_mask_off.
//   uint8   : shift=0 off=0
//   int32   : shift=2 off=0  (little-endian low byte)
//   float32 : shift=2 off=3  (1.0f high byte = 0x3f)
__device__ int g_mask_shift;
__device__ int g_mask_off;

__global__ void detect_mask_dtype_kernel(const unsigned char* __restrict__ m) {
    // Single thread. Scan first 4096 bytes (mask has >= 4M elements in any dtype).
    bool i32_ok = true;   // bytes %4!=0 all zero, %4==0 in {0,1}
    bool f32_ok = true;   // dwords in {0, 0x3f800000}
    for (int i = 0; i < 4096; i++) {
        unsigned char b = m[i];
        int r = i & 3;
        if (r != 0) { if (b != 0) i32_ok = false; }
        else        { if (b > 1)  i32_ok = false; }
    }
    const unsigned int* md = reinterpret_cast<const unsigned int*>(m);
    for (int i = 0; i < 1024; i++) {
        unsigned int d = md[i];
        if (d != 0u && d != 0x3f800000u) f32_ok = false;
    }
    if (i32_ok)      { g_mask_shift = 2; g_mask_off = 0; }
    else if (f32_ok) { g_mask_shift = 2; g_mask_off = 3; }
    else             { g_mask_shift = 0; g_mask_off = 0; }
}

__device__ __forceinline__ unsigned long long ffma2(unsigned long long a,
                                                    unsigned long long b,
                                                    unsigned long long c) {
    unsigned long long d;
    asm("fma.rn.f32x2 %0, %1, %2, %3;" : "=l"(d) : "l"(a), "l"(b), "l"(c));
    return d;
}
__device__ __forceinline__ float f2lo(unsigned long long x) {
    return __uint_as_float((unsigned int)x);
}
__device__ __forceinline__ float f2hi(unsigned long long x) {
    return __uint_as_float((unsigned int)(x >> 32));
}

__global__ void __launch_bounds__(NTHREADS, 1)
attn_fused_kernel(const float* __restrict__ Kg,
                  const float* __restrict__ Qg,
                  const float* __restrict__ Vg,
                  const unsigned char* __restrict__ Mg,
                  float* __restrict__ Og,
                  float* __restrict__ Wg)
{
    extern __shared__ float sm[];
    float* Qs = sm + OFF_QS;
    float* Ks = sm + OFF_KS;
    float* VT = sm + OFF_VT;
    float* P  = sm + OFF_P;
    float* rs = sm + OFF_RS;

    const int bh = blockIdx.y;             // 0..63
    const int qt = blockIdx.x;             // 0..127
    const int t  = threadIdx.x;
    const int q0 = qt * QT;

    const int mshift = g_mask_shift;
    const int moff   = g_mask_off;

    const float* Qbh = Qg + (size_t)bh * Ss * Dd;
    const float* Kbh = Kg + (size_t)bh * Ss * Dd;
    const float* Vbh = Vg + (size_t)bh * Ss * Dd;

    if (t < QT) rs[t] = 0.0f;

    // ---- load Q tile (QT x Dd) into Qs ----
    {
        const int row = t >> 4;            // 0..15
        const int dc  = (t & 15) * 4;      // 0..60
        float4 v = *reinterpret_cast<const float4*>(Qbh + (size_t)(q0 + row) * Dd + dc);
        *reinterpret_cast<float4*>(Qs + row * KPAD + dc) = v;
    }

    // GEMM1 thread map: 4q x 2k micro-tile
    const int qg  = t >> 6;                // 0..3
    const int kk  = t & 63;                // k cols {kk, kk+64}
    // GEMM2 thread map: 2q x 2d micro-tile
    const int qg2 = t >> 5;                // 0..7
    const int dg  = t & 31;                // d cols {dg, dg+32}

    float rsum[4] = {0.f, 0.f, 0.f, 0.f};
    unsigned long long oacc[2][2] = {{0ull, 0ull}, {0ull, 0ull}};

    for (int kb0 = 0; kb0 < Ss; kb0 += KT) {
        // ---- cooperative load K tile -> Ks, V tile -> VT (transposed) ----
        #pragma unroll
        for (int i = 0; i < 8; i++) {
            int linear = t + NTHREADS * i;         // 0..2047
            int row = linear >> 4;                 // key row 0..127
            int dc  = (linear & 15) * 4;
            float4 kv = *reinterpret_cast<const float4*>(Kbh + (size_t)(kb0 + row) * Dd + dc);
            *reinterpret_cast<float4*>(Ks + row * KPAD + dc) = kv;
            float4 vv = *reinterpret_cast<const float4*>(Vbh + (size_t)(kb0 + row) * Dd + dc);
            VT[(dc + 0) * VPAD + row] = vv.x;
            VT[(dc + 1) * VPAD + row] = vv.y;
            VT[(dc + 2) * VPAD + row] = vv.z;
            VT[(dc + 3) * VPAD + row] = vv.w;
        }
        __syncthreads();

        // ---- GEMM1: E(16 x 128) = Q(16 x 64) . K^T, f32x2 over d-pairs ----
        unsigned long long acc[4][2];
        #pragma unroll
        for (int qi = 0; qi < 4; qi++) { acc[qi][0] = 0ull; acc[qi][1] = 0ull; }

        #pragma unroll
        for (int dc = 0; dc < Dd; dc += 4) {
            ulonglong2 k0 = *reinterpret_cast<const ulonglong2*>(Ks + kk * KPAD + dc);
            ulonglong2 k1 = *reinterpret_cast<const ulonglong2*>(Ks + (kk + 64) * KPAD + dc);
            #pragma unroll
            for (int qi = 0; qi < 4; qi++) {
                ulonglong2 qv = *reinterpret_cast<const ulonglong2*>(Qs + (4 * qg + qi) * KPAD + dc);
                acc[qi][0] = ffma2(qv.x, k0.x, acc[qi][0]);
                acc[qi][0] = ffma2(qv.y, k0.y, acc[qi][0]);
                acc[qi][1] = ffma2(qv.x, k1.x, acc[qi][1]);
                acc[qi][1] = ffma2(qv.y, k1.y, acc[qi][1]);
            }
        }

        // ---- mask + exp + store P tile, accumulate row sums ----
        #pragma unroll
        for (int qi = 0; qi < 4; qi++) {
            const int qrow = 4 * qg + qi;
            const size_t mrow = (size_t)(q0 + qrow) * Ss;
            #pragma unroll
            for (int ki = 0; ki < 2; ki++) {
                const int gk = kb0 + kk + 64 * ki;
                float e = f2lo(acc[qi][ki]) + f2hi(acc[qi][ki]);
                const size_t midx = ((mrow + gk) << mshift) + moff;
                float p = (Mg[midx] != 0) ? 0.0f : __expf(e * 0.125f);
                P[qrow * Ss + gk] = p;
                rsum[qi] += p;
            }
        }
        __syncthreads();

        // ---- GEMM2: O(16 x 64) += P_tile(16 x 128) . V_tile(128 x 64), f32x2 over k-pairs ----
        #pragma unroll
        for (int kb2 = 0; kb2 < KT; kb2 += 4) {
            ulonglong2 v0 = *reinterpret_cast<const ulonglong2*>(VT + dg * VPAD + kb2);
            ulonglong2 v1 = *reinterpret_cast<const ulonglong2*>(VT + (dg + 32) * VPAD + kb2);
            ulonglong2 p0 = *reinterpret_cast<const ulonglong2*>(P + (2 * qg2 + 0) * Ss + kb0 + kb2);
            ulonglong2 p1 = *reinterpret_cast<const ulonglong2*>(P + (2 * qg2 + 1) * Ss + kb0 + kb2);
            oacc[0][0] = ffma2(p0.x, v0.x, oacc[0][0]);
            oacc[0][0] = ffma2(p0.y, v0.y, oacc[0][0]);
            oacc[0][1] = ffma2(p0.x, v1.x, oacc[0][1]);
            oacc[0][1] = ffma2(p0.y, v1.y, oacc[0][1]);
            oacc[1][0] = ffma2(p1.x, v0.x, oacc[1][0]);
            oacc[1][0] = ffma2(p1.y, v0.y, oacc[1][0]);
            oacc[1][1] = ffma2(p1.x, v1.x, oacc[1][1]);
            oacc[1][1] = ffma2(p1.y, v1.y, oacc[1][1]);
        }
        __syncthreads();   // protect Ks/VT for next iteration's loader
    }

    // ---- reduce row sums ----
    #pragma unroll
    for (int qi = 0; qi < 4; qi++) {
        atomicAdd(&rs[4 * qg + qi], rsum[qi]);
    }
    __syncthreads();

    // ---- write normalized attention weights ----
    {
        const int row = t >> 4;            // 0..15
        const int tk  = t & 15;
        const float inv = 1.0f / rs[row];
        float* wdst = Wg + (size_t)bh * Ss * Ss + (size_t)(q0 + row) * Ss;
        const float* psrc = P + row * Ss;
        #pragma unroll
        for (int j = 0; j < 32; j++) {
            const int k4 = tk * 4 + 64 * j;
            float4 pv = *reinterpret_cast<const float4*>(psrc + k4);
            pv.x *= inv; pv.y *= inv; pv.z *= inv; pv.w *= inv;
            *reinterpret_cast<float4*>(wdst + k4) = pv;
        }
    }

    // ---- write output ----
    {
        #pragma unroll
        for (int qi = 0; qi < 2; qi++) {
            const int qrow = 2 * qg2 + qi;
            const float inv = 1.0f / rs[qrow];
            float* odst = Og + (size_t)bh * Ss * Dd + (size_t)(q0 + qrow) * Dd;
            #pragma unroll
            for (int di = 0; di < 2; di++) {
                float v = (f2lo(oacc[qi][di]) + f2hi(oacc[qi][di])) * inv;
                odst[dg + 32 * di] = v;
            }
        }
    }
}

extern "C" void kernel_launch(void* const* d_in, const int* in_sizes, int n_in,
                              void* d_out, int out_size) {
    // Identify mask by element count (S*S); the remaining three, in order,
    // are key, query, value (true for both dict order and alphabetical order).
    const int mask_elems = Ss * Ss;
    int mask_idx = -1;
    for (int i = 0; i < n_in; i++) {
        if (in_sizes[i] == mask_elems) { mask_idx = i; break; }
    }
    if (mask_idx < 0) mask_idx = 3;  // fallback: last input

    const float* kqv[3];
    int w = 0;
    for (int i = 0; i < n_in && w < 3; i++) {
        if (i == mask_idx) continue;
        kqv[w++] = (const float*)d_in[i];
    }
    const float* Kg = kqv[0];
    const float* Qg = kqv[1];
    const float* Vg = kqv[2];
    const unsigned char* Mg = (const unsigned char*)d_in[mask_idx];

    float* Og = (float*)d_out;                                  // [B,H,S,D]
    float* Wg = (float*)d_out + (size_t)Bb * Hh * Ss * Dd;      // [B,H,S,S]

    cudaFuncSetAttribute(attn_fused_kernel,
                         cudaFuncAttributeMaxDynamicSharedMemorySize, SMEM_BYTES);

    detect_mask_dtype_kernel<<<1, 1>>>(Mg);

    dim3 grid(Ss / QT, Bb * Hh);
    attn_fused_kernel<<<grid, NTHREADS, SMEM_BYTES>>>(Kg, Qg, Vg, Mg, Og, Wg);
}